// round 8
// baseline (speedup 1.0000x reference)
#include <cuda_runtime.h>
#include <cuda_fp16.h>
#include <stdint.h>
#include <math.h>

#define Bb 4
#define Ss 2048
#define Dd 1024
#define Hh 16
#define Nn 256
#define DDd 64

// ---------------- scratch (device globals; no allocation allowed) ----------
__device__ __half g_U[9216 * 1024];          // pooled GEMM A fp16 [x][d][b][t] x K
__device__ __half g_G[9216 * 1024];          // projection GEMM outputs (fp16)
__device__ __half g_Wh[4 * 1024 * 1024];     // transposed weights [N,K] fp16 (q,k,v,c)
__device__ float g_pool[3 * Bb * Hh * Nn * DDd];  // [x][b][h][t][dd]
__device__ float g_attn[Bb * Hh * Nn * DDd];      // [b][h][t][dd]
__device__ __half g_OP[1024 * 1024];         // up-proj output fp16 [b*t][c]

// ---------------- PTX helpers ----------------------------------------------
static __device__ __forceinline__ uint32_t smem_u32(const void* p) {
    uint32_t r;
    asm("{ .reg .u64 t; cvta.to.shared.u64 t, %1; cvt.u32.u64 %0, t; }" : "=r"(r) : "l"(p));
    return r;
}
static __device__ __forceinline__ void cp16(uint32_t dst, const void* src) {
    asm volatile("cp.async.cg.shared.global [%0], [%1], 16;" :: "r"(dst), "l"(src));
}
#define CP_COMMIT() asm volatile("cp.async.commit_group;" ::: "memory")
#define CP_WAIT1()  asm volatile("cp.async.wait_group 1;" ::: "memory")

static __device__ __forceinline__ void ldsm_x4(uint32_t* r, uint32_t addr) {
    asm volatile("ldmatrix.sync.aligned.m8n8.x4.shared.b16 {%0,%1,%2,%3}, [%4];"
                 : "=r"(r[0]), "=r"(r[1]), "=r"(r[2]), "=r"(r[3]) : "r"(addr));
}
static __device__ __forceinline__ void mma_f16(float* c, const uint32_t* a, const uint32_t* b) {
    asm volatile(
        "mma.sync.aligned.m16n8k16.row.col.f32.f16.f16.f32 "
        "{%0,%1,%2,%3}, {%4,%5,%6,%7}, {%8,%9}, {%0,%1,%2,%3};"
        : "+f"(c[0]), "+f"(c[1]), "+f"(c[2]), "+f"(c[3])
        : "r"(a[0]), "r"(a[1]), "r"(a[2]), "r"(a[3]), "r"(b[0]), "r"(b[1]));
}

static __device__ __forceinline__ float4 f4add(float4 a, float4 b) {
    return make_float4(a.x + b.x, a.y + b.y, a.z + b.z, a.w + b.w);
}

// ---------------------------------------------------------------------------
// Pool kernel (sliding-window): each thread owns 4 channels (float4) and walks
// 64 consecutive pooled positions, reading every input row exactly once.
// For pooled pos t: s_d = sum_{j in [max(0,8t-7), 8t]} x[j+d-2]  (d=0,1,2)
//   rows new[0..7] = 8t-7..8t (OOB -> 0), prev0=row 8t-9, prev1=row 8t-8:
//   s0 = prev0+prev1+sum(new[0..5]); s1 = prev1+sum(new[0..6]); s2 = sum(new[0..7])
// Writes fp16 GEMM-A rows: row = ((x*3+d)*Bb+b)*Nn + t.
// ---------------------------------------------------------------------------
__global__ void __launch_bounds__(256) pool_kernel(const float* __restrict__ q,
                                                   const float* __restrict__ k,
                                                   const float* __restrict__ v) {
    const int tr = blockIdx.x;          // t-range: 64 pooled steps
    const int b = blockIdx.y, x = blockIdx.z;
    const float* src = (x == 0) ? q : ((x == 1) ? k : v);
    const float4* S = (const float4*)(src + (size_t)b * Ss * Dd);
    const int c4 = threadIdx.x;         // float4 column index (0..255)
    const int t0 = tr * 64;

    float4 zero = make_float4(0.f, 0.f, 0.f, 0.f);
    int r0 = 8 * t0 - 9, r1 = 8 * t0 - 8;
    float4 prev0 = (r0 >= 0) ? S[(size_t)r0 * 256 + c4] : zero;
    float4 prev1 = (r1 >= 0) ? S[(size_t)r1 * 256 + c4] : zero;

    for (int t = t0; t < t0 + 64; t++) {
        float4 nw[8];
        #pragma unroll
        for (int kk = 0; kk < 8; kk++) {
            int rr = 8 * t - 7 + kk;
            nw[kk] = (rr >= 0) ? S[(size_t)rr * 256 + c4] : zero;
        }
        float4 p6 = f4add(f4add(f4add(nw[0], nw[1]), f4add(nw[2], nw[3])), f4add(nw[4], nw[5]));
        float4 s0 = f4add(f4add(prev0, prev1), p6);
        float4 s1 = f4add(prev1, f4add(p6, nw[6]));
        float4 s2 = f4add(p6, f4add(nw[6], nw[7]));
        float4 sv[3] = {s0, s1, s2};
        #pragma unroll
        for (int d = 0; d < 3; d++) {
            size_t row = (((size_t)(x * 3 + d)) * Bb + b) * Nn + t;
            __half2* dst = (__half2*)g_U + row * 512 + c4 * 2;
            dst[0] = __floats2half2_rn(sv[d].x, sv[d].y);
            dst[1] = __floats2half2_rn(sv[d].z, sv[d].w);
        }
        prev0 = nw[6];
        prev1 = nw[7];
    }
}

// ---------------------------------------------------------------------------
// Weight prep: transpose W [K,N] -> [N,K], round to fp16.
// ---------------------------------------------------------------------------
__global__ void __launch_bounds__(256) wprep_kernel(const float* __restrict__ W0,
                                                    const float* __restrict__ W1,
                                                    const float* __restrict__ W2,
                                                    const float* __restrict__ W3) {
    const int z = blockIdx.z;
    const float* W = (z == 0) ? W0 : ((z == 1) ? W1 : ((z == 2) ? W2 : W3));
    __half* Oh = g_Wh + (size_t)z * 1024 * 1024;
    __shared__ float tile[32][33];
    const int n0 = blockIdx.x * 32, k0 = blockIdx.y * 32;
    const int tx = threadIdx.x & 31, ty = threadIdx.x >> 5;
    #pragma unroll
    for (int j = 0; j < 4; j++)
        tile[ty + j * 8][tx] = W[(size_t)(k0 + ty + j * 8) * 1024 + n0 + tx];
    __syncthreads();
    #pragma unroll
    for (int j = 0; j < 4; j++) {
        float val = tile[tx][ty + j * 8];
        Oh[(size_t)(n0 + ty + j * 8) * 1024 + k0 + tx] = __float2half_rn(val);
    }
}

// ---------------------------------------------------------------------------
// HMMA fp16 GEMM: C[M,1024] = A @ B^T, A,B fp16, fp32 accumulate.
// CTA tile (64*MI) x 128, 3-stage cp.async pipeline (K-step 64), 8 warps
// (4 in M x 2 in N). SMEM rows padded to 144B -> conflict-free ldmatrix
// (stride 144 = 36 banks -> rows hit distinct 4-bank groups).
// Loads issued BEFORE the MMA phase each iteration.
// BCAST=0: C is __half* (fp16 out). BCAST=1: C is float*, each row written
// to 8 broadcast rows of d_out [B,S,D].
// ---------------------------------------------------------------------------
#define BROWS 128
#define ROWB 144

template <int MI, int BCAST>
__global__ void __launch_bounds__(256) gemm_tc(
        const __half* __restrict__ A,
        const __half* __restrict__ B0, const __half* __restrict__ B1,
        const __half* __restrict__ B2,
        void* __restrict__ Cv, const float* __restrict__ bias, int mblocks_per_x) {
    constexpr int CTAM = 64 * MI;
    constexpr int ASZ = CTAM * ROWB;
    constexpr int BSZ = BROWS * ROWB;
    constexpr int STAGE = ASZ + BSZ;
    constexpr int NCH = 16;              // K chunks of 64

    extern __shared__ char dsm[];
    const uint32_t sbase = smem_u32(dsm);
    const int tid = threadIdx.x;
    const int wid = tid >> 5, lane = tid & 31;
    const int bn = blockIdx.x, bm = blockIdx.y;
    const int x = bm / mblocks_per_x;
    const __half* Bh = (x == 0) ? B0 : ((x == 1) ? B1 : B2);

    const int warpM = wid >> 1;          // 0..3
    const int warpN = wid & 1;           // 0..1
    const uint32_t aOff = (uint32_t)((warpM * 16 * MI + (lane & 15)) * ROWB + (lane >> 4) * 16);
    const uint32_t bOff = (uint32_t)(ASZ +
        (warpN * 64 + ((lane >> 4) & 1) * 8 + (lane & 7)) * ROWB + ((lane >> 3) & 1) * 16);

    float acc[MI][8][4];
    #pragma unroll
    for (int mi = 0; mi < MI; mi++)
        #pragma unroll
        for (int ni = 0; ni < 8; ni++)
            #pragma unroll
            for (int j = 0; j < 4; j++) acc[mi][ni][j] = 0.f;

    auto load_chunk = [&](int ch, int st) {
        const uint32_t bb = sbase + st * STAGE;
        const int kof = ch * 64;
        #pragma unroll
        for (int it = 0; it < 2 * MI; it++) {   // A: CTAM rows * 8 cp16
            int idx = tid + it * 256;
            int r = idx >> 3, qq = idx & 7;
            uint32_t dst = bb + r * ROWB + qq * 16;
            size_t g = (size_t)(bm * CTAM + r) * 1024 + kof + qq * 8;
            cp16(dst, A + g);
        }
        #pragma unroll
        for (int it = 0; it < 4; it++) {        // B: 128 rows * 8 cp16
            int idx = tid + it * 256;
            int r = idx >> 3, qq = idx & 7;
            uint32_t dst = bb + ASZ + r * ROWB + qq * 16;
            size_t g = (size_t)(bn * BROWS + r) * 1024 + kof + qq * 8;
            cp16(dst, Bh + g);
        }
        CP_COMMIT();
    };

    // Prologue: fill 2 of 3 stages
    load_chunk(0, 0);
    load_chunk(1, 1);

    for (int i = 0; i < NCH; i++) {
        CP_WAIT1();              // chunk i resident (<=1 group still in flight)
        __syncthreads();         // all warps done with chunk i-1 before overwrite
        if (i + 2 < NCH) load_chunk(i + 2, (i + 2) % 3);   // overwrites stage of i-1
        else CP_COMMIT();        // keep group count uniform for wait_group
        const uint32_t bb = sbase + (i % 3) * STAGE;
        #pragma unroll
        for (int kk = 0; kk < 4; kk++) {
            uint32_t ah[MI][4];
            #pragma unroll
            for (int mi = 0; mi < MI; mi++)
                ldsm_x4(ah[mi], bb + aOff + mi * 16 * ROWB + kk * 32);
            #pragma unroll
            for (int p = 0; p < 4; p++) {   // 4 n-pairs = 8 n8 tiles
                uint32_t b4[4];
                ldsm_x4(b4, bb + bOff + p * 16 * ROWB + kk * 32);
                #pragma unroll
                for (int mi = 0; mi < MI; mi++) {
                    mma_f16(acc[mi][2 * p],     ah[mi], b4);
                    mma_f16(acc[mi][2 * p + 1], ah[mi], b4 + 2);
                }
            }
        }
    }

    // Epilogue
    const int row0 = bm * CTAM + warpM * 16 * MI + (lane >> 2);
    const int col0 = bn * 128 + warpN * 64 + (lane & 3) * 2;
    #pragma unroll
    for (int mi = 0; mi < MI; mi++) {
        #pragma unroll
        for (int ni = 0; ni < 8; ni++) {
            int r = row0 + mi * 16;
            int c = col0 + ni * 8;
            if (BCAST) {
                float* C = (float*)Cv;
                float b0 = bias ? bias[c] : 0.f, b1 = bias ? bias[c + 1] : 0.f;
                float2 v0 = make_float2(acc[mi][ni][0] + b0, acc[mi][ni][1] + b1);
                float2 v1 = make_float2(acc[mi][ni][2] + b0, acc[mi][ni][3] + b1);
                // r in [0,1024): b = r>>8, t = r&255 -> out rows b*2048 + 8t + rep
                int rb = r >> 8, rt = r & 255;
                float* o0 = C + ((size_t)rb * Ss + rt * 8) * 1024 + c;
                int r8 = r + 8;
                int rb2 = r8 >> 8, rt2 = r8 & 255;
                float* o1 = C + ((size_t)rb2 * Ss + rt2 * 8) * 1024 + c;
                #pragma unroll
                for (int rep = 0; rep < 8; rep++) {
                    *(float2*)(o0 + rep * 1024) = v0;
                    *(float2*)(o1 + rep * 1024) = v1;
                }
            } else {
                __half* C = (__half*)Cv;
                *(__half2*)&C[(size_t)r * 1024 + c] =
                    __floats2half2_rn(acc[mi][ni][0], acc[mi][ni][1]);
                *(__half2*)&C[(size_t)(r + 8) * 1024 + c] =
                    __floats2half2_rn(acc[mi][ni][2], acc[mi][ni][3]);
            }
        }
    }
}

// ---------------------------------------------------------------------------
// Combine: fold conv weights + biases + norm scale + /8 into pooled q/k/v.
// ---------------------------------------------------------------------------
__global__ void __launch_bounds__(256) combine_kernel(
        const float* __restrict__ wcq, const float* __restrict__ bcq, const float* __restrict__ bq,
        const float* __restrict__ wck, const float* __restrict__ bck, const float* __restrict__ bk,
        const float* __restrict__ wcv, const float* __restrict__ bcv, const float* __restrict__ bv) {
    const int t = blockIdx.x, b = blockIdx.y, x = blockIdx.z;
    const float* wc = (x == 0) ? wcq : ((x == 1) ? wck : wcv);
    const float* bc = (x == 0) ? bcq : ((x == 1) ? bck : bcv);
    const float* bd = (x == 0) ? bq  : ((x == 1) ? bk  : bv);
    const float scale = (x == 2) ? 1.0f : 0.35355339059327379f;  // 64^-0.25

    float cJ, c0, c1, c2;
    if (t == 0)      { cJ = 1.f; c0 = 0.f; c1 = 0.f; c2 = 1.f; }
    else if (t == 1) { cJ = 8.f; c0 = 7.f; c1 = 8.f; c2 = 8.f; }
    else             { cJ = 8.f; c0 = 8.f; c1 = 8.f; c2 = 8.f; }

    const size_t ds = (size_t)Bb * Nn * Dd;
    const size_t base0 = ((((size_t)x * 3 + 0) * Bb + b) * Nn + t) * Dd;

    for (int c = threadIdx.x; c < Dd; c += 256) {
        float G0 = __half2float(g_G[base0 + c]);
        float G1 = __half2float(g_G[base0 + ds + c]);
        float G2 = __half2float(g_G[base0 + 2 * ds + c]);
        float bdc = bd[c];
        float val = cJ * bc[c] + scale * (wc[c]          * (G0 + c0 * bdc) +
                                          wc[Dd + c]     * (G1 + c1 * bdc) +
                                          wc[2 * Dd + c] * (G2 + c2 * bdc));
        val *= 0.125f;
        int h = c >> 6, dd = c & 63;
        g_pool[((((size_t)x * Bb + b) * Hh + h) * Nn + t) * DDd + dd] = val;
    }
}

// ---------------------------------------------------------------------------
// Attention per (b,h): thread i = query row i, online softmax, causal skip.
// ---------------------------------------------------------------------------
__global__ void __launch_bounds__(256) attn_kernel() {
    const int bh = blockIdx.x;
    __shared__ float sK[64][DDd];
    __shared__ float sV[64][DDd];
    const float* qp = g_pool + ((size_t)0 * Bb * Hh + bh) * Nn * DDd;
    const float* kp = g_pool + ((size_t)1 * Bb * Hh + bh) * Nn * DDd;
    const float* vp = g_pool + ((size_t)2 * Bb * Hh + bh) * Nn * DDd;
    const int i = threadIdx.x;

    float qreg[DDd];
    #pragma unroll
    for (int d = 0; d < DDd; d++) qreg[d] = qp[(size_t)i * DDd + d];

    float mi = -1e30f, li = 0.f;
    float acc[DDd];
    #pragma unroll
    for (int d = 0; d < DDd; d++) acc[d] = 0.f;

    for (int kt = 0; kt < Nn; kt += 64) {
        for (int idx = threadIdx.x; idx < 64 * DDd / 4; idx += 256) {
            ((float4*)&sK[0][0])[idx] = ((const float4*)(kp + (size_t)kt * DDd))[idx];
            ((float4*)&sV[0][0])[idx] = ((const float4*)(vp + (size_t)kt * DDd))[idx];
        }
        __syncthreads();
        int mmax = i - kt; if (mmax > 63) mmax = 63;
        for (int m = 0; m <= mmax; m++) {
            float d0 = 0.f, d1 = 0.f, d2 = 0.f, d3 = 0.f;
            #pragma unroll
            for (int d = 0; d < DDd; d += 4) {
                d0 += qreg[d + 0] * sK[m][d + 0];
                d1 += qreg[d + 1] * sK[m][d + 1];
                d2 += qreg[d + 2] * sK[m][d + 2];
                d3 += qreg[d + 3] * sK[m][d + 3];
            }
            float dot = (d0 + d1) + (d2 + d3);
            if (dot > mi) {
                float f = __expf(mi - dot);
                li *= f;
                #pragma unroll
                for (int d = 0; d < DDd; d++) acc[d] *= f;
                mi = dot;
            }
            float p = __expf(dot - mi);
            li += p;
            #pragma unroll
            for (int d = 0; d < DDd; d++) acc[d] += p * sV[m][d];
        }
        __syncthreads();
    }

    float inv = 1.0f / li;
    float* outp = g_attn + ((size_t)bh * Nn + i) * DDd;
    #pragma unroll
    for (int d = 0; d < DDd; d++) outp[d] = acc[d] * inv;
}

// ---------------------------------------------------------------------------
// Up-projection (Wup [64,64] per head) + merge -> fp16 rows for Wc GEMM
// ---------------------------------------------------------------------------
__global__ void __launch_bounds__(256) up_kernel(const float* __restrict__ Wup,
                                                 const float* __restrict__ bup) {
    const int bt = blockIdx.x;
    const int b = bt >> 8, t = bt & 255;
    __shared__ float sW[DDd * DDd];
    __shared__ float sIn[Hh * DDd];
    for (int idx = threadIdx.x; idx < DDd * DDd; idx += 256) sW[idx] = Wup[idx];
    for (int idx = threadIdx.x; idx < Hh * DDd; idx += 256) {
        int h = idx >> 6, dd = idx & 63;
        sIn[idx] = g_attn[(((size_t)b * Hh + h) * Nn + t) * DDd + dd];
    }
    __syncthreads();
    for (int c = threadIdx.x; c < Dd; c += 256) {
        int h = c >> 6, ddp = c & 63;
        float s = bup[ddp];
        #pragma unroll
        for (int dd = 0; dd < DDd; dd++) s += sIn[h * DDd + dd] * sW[dd * DDd + ddp];
        g_OP[((size_t)b * Nn + t) * Dd + c] = __float2half_rn(s);
    }
}

// ---------------------------------------------------------------------------
extern "C" void kernel_launch(void* const* d_in, const int* in_sizes, int n_in,
                              void* d_out, int out_size) {
    const float* q   = (const float*)d_in[0];
    const float* k   = (const float*)d_in[1];
    const float* v   = (const float*)d_in[2];
    const float* Wq  = (const float*)d_in[3];
    const float* bq  = (const float*)d_in[4];
    const float* Wk  = (const float*)d_in[5];
    const float* bk  = (const float*)d_in[6];
    const float* Wv  = (const float*)d_in[7];
    const float* bv  = (const float*)d_in[8];
    const float* Wup = (const float*)d_in[9];
    const float* bup = (const float*)d_in[10];
    const float* Wc  = (const float*)d_in[11];
    const float* bc  = (const float*)d_in[12];
    const float* wcq = (const float*)d_in[13];
    const float* bcq = (const float*)d_in[14];
    const float* wck = (const float*)d_in[15];
    const float* bck = (const float*)d_in[16];
    const float* wcv = (const float*)d_in[17];
    const float* bcv = (const float*)d_in[18];

    __half *pU, *pWh, *pOP, *pG;
    cudaGetSymbolAddress((void**)&pU, g_U);
    cudaGetSymbolAddress((void**)&pWh, g_Wh);
    cudaGetSymbolAddress((void**)&pOP, g_OP);
    cudaGetSymbolAddress((void**)&pG, g_G);

    // smem: MI=2: 3 * (128+128)*144 = 110592 ; MI=1: 3 * (64+128)*144 = 82944
    const int SM2 = 3 * (128 + 128) * ROWB;
    const int SM1 = 3 * (64 + 128) * ROWB;
    cudaFuncSetAttribute((const void*)gemm_tc<2, 0>, cudaFuncAttributeMaxDynamicSharedMemorySize, SM2);
    cudaFuncSetAttribute((const void*)gemm_tc<1, 1>, cudaFuncAttributeMaxDynamicSharedMemorySize, SM1);

    // 1. Weight transpose + fp16 round (Wq,Wk,Wv,Wc)
    wprep_kernel<<<dim3(32, 32, 4), 256>>>(Wq, Wk, Wv, Wc);

    // 2. Pooled GEMM inputs (dw-conv decomposition + causal pool), fp16
    pool_kernel<<<dim3(4, Bb, 3), 256>>>(q, k, v);

    // 3. Fused projection GEMMs: [9216,1024] @ per-x [1024,1024]^T -> fp16 G
    const size_t wstep = (size_t)1024 * 1024;
    gemm_tc<2, 0><<<dim3(8, 72), 256, SM2>>>(
        pU, pWh + 0 * wstep, pWh + 1 * wstep, pWh + 2 * wstep,
        pG, nullptr, 24);

    // 4. Combine conv weights/biases/scale -> pooled q/k/v
    combine_kernel<<<dim3(Nn, Bb, 3), 256>>>(wcq, bcq, bq, wck, bck, bk, wcv, bcv, bv);

    // 5. Causal attention over pooled tokens
    attn_kernel<<<Bb * Hh, 256>>>();

    // 6. Per-head Wup + merge heads -> fp16
    up_kernel<<<Bb * Nn, 256>>>(Wup, bup);

    // 7. Final dense Wc (+bias), epilogue broadcasts each row to 8 seq positions
    gemm_tc<1, 1><<<dim3(8, 16), 256, SM1>>>(
        pOP, pWh + 3 * wstep, pWh + 3 * wstep, pWh + 3 * wstep,
        (void*)d_out, bc, 16);
}

// round 9
// speedup vs baseline: 1.4720x; 1.4720x over previous
#include <cuda_runtime.h>
#include <cuda_fp16.h>
#include <stdint.h>
#include <math.h>

#define Bb 4
#define Ss 2048
#define Dd 1024
#define Hh 16
#define Nn 256
#define DDd 64

// ---------------- scratch (device globals; no allocation allowed) ----------
__device__ __half g_U[9216 * 1024];          // pooled GEMM A fp16 [x][d][b][t] x K
__device__ __half g_G[9216 * 1024];          // projection GEMM outputs (fp16)
__device__ __half g_Wh[4 * 1024 * 1024];     // transposed weights [N,K] fp16 (q,k,v,c)
__device__ float g_pool[3 * Bb * Hh * Nn * DDd];  // [x][b][h][t][dd]
__device__ float g_attn[Bb * Hh * Nn * DDd];      // [b][h][t][dd]
__device__ __half g_OP[1024 * 1024];         // up-proj output fp16 [b*t][c]

// ---------------- PTX helpers ----------------------------------------------
static __device__ __forceinline__ uint32_t smem_u32(const void* p) {
    uint32_t r;
    asm("{ .reg .u64 t; cvta.to.shared.u64 t, %1; cvt.u32.u64 %0, t; }" : "=r"(r) : "l"(p));
    return r;
}
static __device__ __forceinline__ void cp16(uint32_t dst, const void* src) {
    asm volatile("cp.async.cg.shared.global [%0], [%1], 16;" :: "r"(dst), "l"(src));
}
#define CP_COMMIT() asm volatile("cp.async.commit_group;" ::: "memory")
#define CP_WAIT1()  asm volatile("cp.async.wait_group 1;" ::: "memory")

static __device__ __forceinline__ void ldsm_x4(uint32_t* r, uint32_t addr) {
    asm volatile("ldmatrix.sync.aligned.m8n8.x4.shared.b16 {%0,%1,%2,%3}, [%4];"
                 : "=r"(r[0]), "=r"(r[1]), "=r"(r[2]), "=r"(r[3]) : "r"(addr));
}
static __device__ __forceinline__ void mma_f16(float* c, const uint32_t* a, const uint32_t* b) {
    asm volatile(
        "mma.sync.aligned.m16n8k16.row.col.f32.f16.f16.f32 "
        "{%0,%1,%2,%3}, {%4,%5,%6,%7}, {%8,%9}, {%0,%1,%2,%3};"
        : "+f"(c[0]), "+f"(c[1]), "+f"(c[2]), "+f"(c[3])
        : "r"(a[0]), "r"(a[1]), "r"(a[2]), "r"(a[3]), "r"(b[0]), "r"(b[1]));
}

static __device__ __forceinline__ float4 f4add(float4 a, float4 b) {
    return make_float4(a.x + b.x, a.y + b.y, a.z + b.z, a.w + b.w);
}

// ---------------------------------------------------------------------------
// Pool kernel (sliding-window, 8 steps/block -> 384 CTAs): thread owns 4
// channels, walks 8 consecutive pooled steps, each input row read once.
// For pooled pos t: s_d = sum_{j in [max(0,8t-7), 8t]} x[j+d-2]  (d=0,1,2)
//   new[0..7] = rows 8t-7..8t (OOB -> 0), prev0 = row 8t-9, prev1 = row 8t-8:
//   s0 = prev0+prev1+sum(new[0..5]); s1 = prev1+sum(new[0..6]); s2 = sum(new[0..7])
// Writes fp16 GEMM-A rows: row = ((x*3+d)*Bb+b)*Nn + t.
// ---------------------------------------------------------------------------
#define TSTEP 8
__global__ void __launch_bounds__(256) pool_kernel(const float* __restrict__ q,
                                                   const float* __restrict__ k,
                                                   const float* __restrict__ v) {
    const int tr = blockIdx.x;          // range of TSTEP pooled steps
    const int b = blockIdx.y, x = blockIdx.z;
    const float* src = (x == 0) ? q : ((x == 1) ? k : v);
    const float4* S = (const float4*)(src + (size_t)b * Ss * Dd);
    const int c4 = threadIdx.x;         // float4 column index (0..255)
    const int t0 = tr * TSTEP;

    float4 zero = make_float4(0.f, 0.f, 0.f, 0.f);
    int r0 = 8 * t0 - 9, r1 = 8 * t0 - 8;
    float4 prev0 = (r0 >= 0) ? S[(size_t)r0 * 256 + c4] : zero;
    float4 prev1 = (r1 >= 0) ? S[(size_t)r1 * 256 + c4] : zero;

    #pragma unroll
    for (int t = t0; t < t0 + TSTEP; t++) {
        float4 nw[8];
        #pragma unroll
        for (int kk = 0; kk < 8; kk++) {
            int rr = 8 * t - 7 + kk;
            nw[kk] = (rr >= 0) ? S[(size_t)rr * 256 + c4] : zero;
        }
        float4 p6 = f4add(f4add(f4add(nw[0], nw[1]), f4add(nw[2], nw[3])), f4add(nw[4], nw[5]));
        float4 s0 = f4add(f4add(prev0, prev1), p6);
        float4 s1 = f4add(prev1, f4add(p6, nw[6]));
        float4 s2 = f4add(p6, f4add(nw[6], nw[7]));
        float4 sv[3] = {s0, s1, s2};
        #pragma unroll
        for (int d = 0; d < 3; d++) {
            size_t row = (((size_t)(x * 3 + d)) * Bb + b) * Nn + t;
            __half2* dst = (__half2*)g_U + row * 512 + c4 * 2;
            dst[0] = __floats2half2_rn(sv[d].x, sv[d].y);
            dst[1] = __floats2half2_rn(sv[d].z, sv[d].w);
        }
        prev0 = nw[6];
        prev1 = nw[7];
    }
}

// ---------------------------------------------------------------------------
// Weight prep: transpose W [K,N] -> [N,K], round to fp16.
// ---------------------------------------------------------------------------
__global__ void __launch_bounds__(256) wprep_kernel(const float* __restrict__ W0,
                                                    const float* __restrict__ W1,
                                                    const float* __restrict__ W2,
                                                    const float* __restrict__ W3) {
    const int z = blockIdx.z;
    const float* W = (z == 0) ? W0 : ((z == 1) ? W1 : ((z == 2) ? W2 : W3));
    __half* Oh = g_Wh + (size_t)z * 1024 * 1024;
    __shared__ float tile[32][33];
    const int n0 = blockIdx.x * 32, k0 = blockIdx.y * 32;
    const int tx = threadIdx.x & 31, ty = threadIdx.x >> 5;
    #pragma unroll
    for (int j = 0; j < 4; j++)
        tile[ty + j * 8][tx] = W[(size_t)(k0 + ty + j * 8) * 1024 + n0 + tx];
    __syncthreads();
    #pragma unroll
    for (int j = 0; j < 4; j++) {
        float val = tile[tx][ty + j * 8];
        Oh[(size_t)(n0 + ty + j * 8) * 1024 + k0 + tx] = __float2half_rn(val);
    }
}

// ---------------------------------------------------------------------------
// HMMA fp16 GEMM (reverted to round-6 structure): C = A @ B^T, A,B fp16,
// fp32 accumulate. CTA tile (64*MI) x 128, K-step 32, 3-stage cp.async,
// 8 warps (4 in M x 2 in N). SMEM rows padded to 80B. Loads after MMA phase.
// BCAST=0: C is __half* (fp16 out). BCAST=1: C is float* d_out, each row
// broadcast to 8 sequence rows.
// ---------------------------------------------------------------------------
#define BROWS 128

template <int MI, int BCAST>
__global__ void __launch_bounds__(256) gemm_tc(
        const __half* __restrict__ A,
        const __half* __restrict__ B0, const __half* __restrict__ B1,
        const __half* __restrict__ B2,
        void* __restrict__ Cv, const float* __restrict__ bias, int mblocks_per_x) {
    constexpr int CTAM = 64 * MI;
    constexpr int ASZ = CTAM * 80;
    constexpr int BSZ = BROWS * 80;
    constexpr int STAGE = ASZ + BSZ;

    extern __shared__ char dsm[];
    const uint32_t sbase = smem_u32(dsm);
    const int tid = threadIdx.x;
    const int wid = tid >> 5, lane = tid & 31;
    const int bn = blockIdx.x, bm = blockIdx.y;
    const int x = bm / mblocks_per_x;
    const __half* Bh = (x == 0) ? B0 : ((x == 1) ? B1 : B2);

    const int warpM = wid >> 1;          // 0..3
    const int warpN = wid & 1;           // 0..1
    const uint32_t aOff = (uint32_t)((warpM * 16 * MI + (lane & 15)) * 80 + (lane >> 4) * 16);
    const uint32_t bOff = (uint32_t)(ASZ +
        (warpN * 64 + ((lane >> 4) & 1) * 8 + (lane & 7)) * 80 + ((lane >> 3) & 1) * 16);

    float acc[MI][8][4];
    #pragma unroll
    for (int mi = 0; mi < MI; mi++)
        #pragma unroll
        for (int ni = 0; ni < 8; ni++)
            #pragma unroll
            for (int j = 0; j < 4; j++) acc[mi][ni][j] = 0.f;

    auto load_chunk = [&](int ch, int st) {
        const uint32_t bb = sbase + st * STAGE;
        const int kof = ch * 32;
        #pragma unroll
        for (int it = 0; it < MI; it++) {   // A: CTAM rows * 4 cp16 / 256 thr
            int idx = tid + it * 256;
            int r = idx >> 2, qq = idx & 3;
            uint32_t dst = bb + r * 80 + qq * 16;
            size_t g = (size_t)(bm * CTAM + r) * 1024 + kof + qq * 8;
            cp16(dst, A + g);
        }
        #pragma unroll
        for (int it = 0; it < 2; it++) {    // B: 128 rows * 4 cp16 / 256 thr
            int idx = tid + it * 256;
            int r = idx >> 2, qq = idx & 3;
            uint32_t dst = bb + ASZ + r * 80 + qq * 16;
            size_t g = (size_t)(bn * BROWS + r) * 1024 + kof + qq * 8;
            cp16(dst, Bh + g);
        }
        CP_COMMIT();
    };

    // Prologue: fill 2 of 3 stages
    load_chunk(0, 0);
    load_chunk(1, 1);

    for (int i = 0; i < 32; i++) {
        CP_WAIT1();              // chunk i resident (<=1 group still in flight)
        __syncthreads();         // all warps done with chunk i-1 before overwrite
        const uint32_t bb = sbase + (i % 3) * STAGE;
        #pragma unroll
        for (int kk = 0; kk < 2; kk++) {
            uint32_t ah[MI][4];
            #pragma unroll
            for (int mi = 0; mi < MI; mi++)
                ldsm_x4(ah[mi], bb + aOff + mi * 16 * 80 + kk * 32);
            #pragma unroll
            for (int p = 0; p < 4; p++) {   // 4 n-pairs = 8 n8 tiles
                uint32_t b4[4];
                ldsm_x4(b4, bb + bOff + p * 16 * 80 + kk * 32);
                #pragma unroll
                for (int mi = 0; mi < MI; mi++) {
                    mma_f16(acc[mi][2 * p],     ah[mi], b4);
                    mma_f16(acc[mi][2 * p + 1], ah[mi], b4 + 2);
                }
            }
        }
        if (i + 2 < 32) load_chunk(i + 2, (i + 2) % 3);
        else CP_COMMIT();        // keep group count uniform for wait_group
    }

    // Epilogue
    const int row0 = bm * CTAM + warpM * 16 * MI + (lane >> 2);
    const int col0 = bn * 128 + warpN * 64 + (lane & 3) * 2;
    #pragma unroll
    for (int mi = 0; mi < MI; mi++) {
        #pragma unroll
        for (int ni = 0; ni < 8; ni++) {
            int r = row0 + mi * 16;
            int c = col0 + ni * 8;
            if (BCAST) {
                float* C = (float*)Cv;
                float b0 = bias ? bias[c] : 0.f, b1 = bias ? bias[c + 1] : 0.f;
                float2 v0 = make_float2(acc[mi][ni][0] + b0, acc[mi][ni][1] + b1);
                float2 v1 = make_float2(acc[mi][ni][2] + b0, acc[mi][ni][3] + b1);
                // r in [0,1024): b = r>>8, t = r&255 -> out rows b*2048 + 8t + rep
                int rb = r >> 8, rt = r & 255;
                float* o0 = C + ((size_t)rb * Ss + rt * 8) * 1024 + c;
                int r8 = r + 8;
                int rb2 = r8 >> 8, rt2 = r8 & 255;
                float* o1 = C + ((size_t)rb2 * Ss + rt2 * 8) * 1024 + c;
                #pragma unroll
                for (int rep = 0; rep < 8; rep++) {
                    *(float2*)(o0 + rep * 1024) = v0;
                    *(float2*)(o1 + rep * 1024) = v1;
                }
            } else {
                __half* C = (__half*)Cv;
                *(__half2*)&C[(size_t)r * 1024 + c] =
                    __floats2half2_rn(acc[mi][ni][0], acc[mi][ni][1]);
                *(__half2*)&C[(size_t)(r + 8) * 1024 + c] =
                    __floats2half2_rn(acc[mi][ni][2], acc[mi][ni][3]);
            }
        }
    }
}

// ---------------------------------------------------------------------------
// Combine: fold conv weights + biases + norm scale + /8 into pooled q/k/v.
// ---------------------------------------------------------------------------
__global__ void __launch_bounds__(256) combine_kernel(
        const float* __restrict__ wcq, const float* __restrict__ bcq, const float* __restrict__ bq,
        const float* __restrict__ wck, const float* __restrict__ bck, const float* __restrict__ bk,
        const float* __restrict__ wcv, const float* __restrict__ bcv, const float* __restrict__ bv) {
    const int t = blockIdx.x, b = blockIdx.y, x = blockIdx.z;
    const float* wc = (x == 0) ? wcq : ((x == 1) ? wck : wcv);
    const float* bc = (x == 0) ? bcq : ((x == 1) ? bck : bcv);
    const float* bd = (x == 0) ? bq  : ((x == 1) ? bk  : bv);
    const float scale = (x == 2) ? 1.0f : 0.35355339059327379f;  // 64^-0.25

    float cJ, c0, c1, c2;
    if (t == 0)      { cJ = 1.f; c0 = 0.f; c1 = 0.f; c2 = 1.f; }
    else if (t == 1) { cJ = 8.f; c0 = 7.f; c1 = 8.f; c2 = 8.f; }
    else             { cJ = 8.f; c0 = 8.f; c1 = 8.f; c2 = 8.f; }

    const size_t ds = (size_t)Bb * Nn * Dd;
    const size_t base0 = ((((size_t)x * 3 + 0) * Bb + b) * Nn + t) * Dd;

    for (int c = threadIdx.x; c < Dd; c += 256) {
        float G0 = __half2float(g_G[base0 + c]);
        float G1 = __half2float(g_G[base0 + ds + c]);
        float G2 = __half2float(g_G[base0 + 2 * ds + c]);
        float bdc = bd[c];
        float val = cJ * bc[c] + scale * (wc[c]          * (G0 + c0 * bdc) +
                                          wc[Dd + c]     * (G1 + c1 * bdc) +
                                          wc[2 * Dd + c] * (G2 + c2 * bdc));
        val *= 0.125f;
        int h = c >> 6, dd = c & 63;
        g_pool[((((size_t)x * Bb + b) * Hh + h) * Nn + t) * DDd + dd] = val;
    }
}

// ---------------------------------------------------------------------------
// Attention per (b,h): thread i = query row i, online softmax, causal skip.
// ---------------------------------------------------------------------------
__global__ void __launch_bounds__(256) attn_kernel() {
    const int bh = blockIdx.x;
    __shared__ float sK[64][DDd];
    __shared__ float sV[64][DDd];
    const float* qp = g_pool + ((size_t)0 * Bb * Hh + bh) * Nn * DDd;
    const float* kp = g_pool + ((size_t)1 * Bb * Hh + bh) * Nn * DDd;
    const float* vp = g_pool + ((size_t)2 * Bb * Hh + bh) * Nn * DDd;
    const int i = threadIdx.x;

    float qreg[DDd];
    #pragma unroll
    for (int d = 0; d < DDd; d++) qreg[d] = qp[(size_t)i * DDd + d];

    float mi = -1e30f, li = 0.f;
    float acc[DDd];
    #pragma unroll
    for (int d = 0; d < DDd; d++) acc[d] = 0.f;

    for (int kt = 0; kt < Nn; kt += 64) {
        for (int idx = threadIdx.x; idx < 64 * DDd / 4; idx += 256) {
            ((float4*)&sK[0][0])[idx] = ((const float4*)(kp + (size_t)kt * DDd))[idx];
            ((float4*)&sV[0][0])[idx] = ((const float4*)(vp + (size_t)kt * DDd))[idx];
        }
        __syncthreads();
        int mmax = i - kt; if (mmax > 63) mmax = 63;
        for (int m = 0; m <= mmax; m++) {
            float d0 = 0.f, d1 = 0.f, d2 = 0.f, d3 = 0.f;
            #pragma unroll
            for (int d = 0; d < DDd; d += 4) {
                d0 += qreg[d + 0] * sK[m][d + 0];
                d1 += qreg[d + 1] * sK[m][d + 1];
                d2 += qreg[d + 2] * sK[m][d + 2];
                d3 += qreg[d + 3] * sK[m][d + 3];
            }
            float dot = (d0 + d1) + (d2 + d3);
            if (dot > mi) {
                float f = __expf(mi - dot);
                li *= f;
                #pragma unroll
                for (int d = 0; d < DDd; d++) acc[d] *= f;
                mi = dot;
            }
            float p = __expf(dot - mi);
            li += p;
            #pragma unroll
            for (int d = 0; d < DDd; d++) acc[d] += p * sV[m][d];
        }
        __syncthreads();
    }

    float inv = 1.0f / li;
    float* outp = g_attn + ((size_t)bh * Nn + i) * DDd;
    #pragma unroll
    for (int d = 0; d < DDd; d++) outp[d] = acc[d] * inv;
}

// ---------------------------------------------------------------------------
// Up-projection (Wup [64,64] per head) + merge -> fp16 rows for Wc GEMM
// ---------------------------------------------------------------------------
__global__ void __launch_bounds__(256) up_kernel(const float* __restrict__ Wup,
                                                 const float* __restrict__ bup) {
    const int bt = blockIdx.x;
    const int b = bt >> 8, t = bt & 255;
    __shared__ float sW[DDd * DDd];
    __shared__ float sIn[Hh * DDd];
    for (int idx = threadIdx.x; idx < DDd * DDd; idx += 256) sW[idx] = Wup[idx];
    for (int idx = threadIdx.x; idx < Hh * DDd; idx += 256) {
        int h = idx >> 6, dd = idx & 63;
        sIn[idx] = g_attn[(((size_t)b * Hh + h) * Nn + t) * DDd + dd];
    }
    __syncthreads();
    for (int c = threadIdx.x; c < Dd; c += 256) {
        int h = c >> 6, ddp = c & 63;
        float s = bup[ddp];
        #pragma unroll
        for (int dd = 0; dd < DDd; dd++) s += sIn[h * DDd + dd] * sW[dd * DDd + ddp];
        g_OP[((size_t)b * Nn + t) * Dd + c] = __float2half_rn(s);
    }
}

// ---------------------------------------------------------------------------
extern "C" void kernel_launch(void* const* d_in, const int* in_sizes, int n_in,
                              void* d_out, int out_size) {
    const float* q   = (const float*)d_in[0];
    const float* k   = (const float*)d_in[1];
    const float* v   = (const float*)d_in[2];
    const float* Wq  = (const float*)d_in[3];
    const float* bq  = (const float*)d_in[4];
    const float* Wk  = (const float*)d_in[5];
    const float* bk  = (const float*)d_in[6];
    const float* Wv  = (const float*)d_in[7];
    const float* bv  = (const float*)d_in[8];
    const float* Wup = (const float*)d_in[9];
    const float* bup = (const float*)d_in[10];
    const float* Wc  = (const float*)d_in[11];
    const float* bc  = (const float*)d_in[12];
    const float* wcq = (const float*)d_in[13];
    const float* bcq = (const float*)d_in[14];
    const float* wck = (const float*)d_in[15];
    const float* bck = (const float*)d_in[16];
    const float* wcv = (const float*)d_in[17];
    const float* bcv = (const float*)d_in[18];

    __half *pU, *pWh, *pOP, *pG;
    cudaGetSymbolAddress((void**)&pU, g_U);
    cudaGetSymbolAddress((void**)&pWh, g_Wh);
    cudaGetSymbolAddress((void**)&pOP, g_OP);
    cudaGetSymbolAddress((void**)&pG, g_G);

    // smem: MI=2: 3 * (128*80 + 128*80) = 61440 ; MI=1: 3 * (64*80 + 128*80) = 46080
    const int SM2 = 3 * (128 * 80 + 128 * 80);
    const int SM1 = 3 * (64 * 80 + 128 * 80);
    cudaFuncSetAttribute((const void*)gemm_tc<2, 0>, cudaFuncAttributeMaxDynamicSharedMemorySize, SM2);
    cudaFuncSetAttribute((const void*)gemm_tc<1, 1>, cudaFuncAttributeMaxDynamicSharedMemorySize, SM1);

    // 1. Weight transpose + fp16 round (Wq,Wk,Wv,Wc)
    wprep_kernel<<<dim3(32, 32, 4), 256>>>(Wq, Wk, Wv, Wc);

    // 2. Pooled GEMM inputs (dw-conv decomposition + causal pool), fp16
    pool_kernel<<<dim3(Nn / TSTEP, Bb, 3), 256>>>(q, k, v);

    // 3. Fused projection GEMMs: [9216,1024] @ per-x [1024,1024]^T -> fp16 G
    const size_t wstep = (size_t)1024 * 1024;
    gemm_tc<2, 0><<<dim3(8, 72), 256, SM2>>>(
        pU, pWh + 0 * wstep, pWh + 1 * wstep, pWh + 2 * wstep,
        pG, nullptr, 24);

    // 4. Combine conv weights/biases/scale -> pooled q/k/v
    combine_kernel<<<dim3(Nn, Bb, 3), 256>>>(wcq, bcq, bq, wck, bck, bk, wcv, bcv, bv);

    // 5. Causal attention over pooled tokens
    attn_kernel<<<Bb * Hh, 256>>>();

    // 6. Per-head Wup + merge heads -> fp16
    up_kernel<<<Bb * Nn, 256>>>(Wup, bup);

    // 7. Final dense Wc (+bias), epilogue broadcasts each row to 8 seq positions
    gemm_tc<1, 1><<<dim3(8, 16), 256, SM1>>>(
        pOP, pWh + 3 * wstep, pWh + 3 * wstep, pWh + 3 * wstep,
        (void*)d_out, bc, 16);
}

// round 10
// speedup vs baseline: 1.5077x; 1.0242x over previous
#include <cuda_runtime.h>
#include <cuda_fp16.h>
#include <stdint.h>
#include <math.h>

#define Bb 4
#define Ss 2048
#define Dd 1024
#define Hh 16
#define Nn 256
#define DDd 64

// ---------------- scratch (device globals; no allocation allowed) ----------
__device__ __half g_U[9216 * 1024];          // pooled GEMM A fp16 [x][d][b][t] x K
__device__ __half g_G[9216 * 1024];          // projection GEMM outputs (fp16)
__device__ __half g_Wh[4 * 1024 * 1024];     // transposed weights [N,K] fp16 (q,k,v,c)
__device__ float g_pool[3 * Bb * Hh * Nn * DDd];  // [x][b][h][t][dd]
__device__ float g_attn[Bb * Hh * Nn * DDd];      // [b][h][t][dd]
__device__ __half g_OP[1024 * 1024];         // up-proj output fp16 [b*t][c]

// ---------------- PTX helpers ----------------------------------------------
static __device__ __forceinline__ uint32_t smem_u32(const void* p) {
    uint32_t r;
    asm("{ .reg .u64 t; cvta.to.shared.u64 t, %1; cvt.u32.u64 %0, t; }" : "=r"(r) : "l"(p));
    return r;
}
static __device__ __forceinline__ void cp16(uint32_t dst, const void* src) {
    asm volatile("cp.async.cg.shared.global [%0], [%1], 16;" :: "r"(dst), "l"(src));
}
#define CP_COMMIT() asm volatile("cp.async.commit_group;" ::: "memory")
#define CP_WAIT1()  asm volatile("cp.async.wait_group 1;" ::: "memory")

static __device__ __forceinline__ void ldsm_x4(uint32_t* r, uint32_t addr) {
    asm volatile("ldmatrix.sync.aligned.m8n8.x4.shared.b16 {%0,%1,%2,%3}, [%4];"
                 : "=r"(r[0]), "=r"(r[1]), "=r"(r[2]), "=r"(r[3]) : "r"(addr));
}
static __device__ __forceinline__ void mma_f16(float* c, const uint32_t* a, const uint32_t* b) {
    asm volatile(
        "mma.sync.aligned.m16n8k16.row.col.f32.f16.f16.f32 "
        "{%0,%1,%2,%3}, {%4,%5,%6,%7}, {%8,%9}, {%0,%1,%2,%3};"
        : "+f"(c[0]), "+f"(c[1]), "+f"(c[2]), "+f"(c[3])
        : "r"(a[0]), "r"(a[1]), "r"(a[2]), "r"(a[3]), "r"(b[0]), "r"(b[1]));
}

static __device__ __forceinline__ float4 f4add(float4 a, float4 b) {
    return make_float4(a.x + b.x, a.y + b.y, a.z + b.z, a.w + b.w);
}

// ---------------------------------------------------------------------------
// Pool kernel (sliding-window, 8 steps/block -> 384 CTAs): thread owns 4
// channels, walks 8 consecutive pooled steps, each input row read once.
// ---------------------------------------------------------------------------
#define TSTEP 8
__global__ void __launch_bounds__(256) pool_kernel(const float* __restrict__ q,
                                                   const float* __restrict__ k,
                                                   const float* __restrict__ v) {
    const int tr = blockIdx.x;          // range of TSTEP pooled steps
    const int b = blockIdx.y, x = blockIdx.z;
    const float* src = (x == 0) ? q : ((x == 1) ? k : v);
    const float4* S = (const float4*)(src + (size_t)b * Ss * Dd);
    const int c4 = threadIdx.x;         // float4 column index (0..255)
    const int t0 = tr * TSTEP;

    float4 zero = make_float4(0.f, 0.f, 0.f, 0.f);
    int r0 = 8 * t0 - 9, r1 = 8 * t0 - 8;
    float4 prev0 = (r0 >= 0) ? S[(size_t)r0 * 256 + c4] : zero;
    float4 prev1 = (r1 >= 0) ? S[(size_t)r1 * 256 + c4] : zero;

    #pragma unroll
    for (int t = t0; t < t0 + TSTEP; t++) {
        float4 nw[8];
        #pragma unroll
        for (int kk = 0; kk < 8; kk++) {
            int rr = 8 * t - 7 + kk;
            nw[kk] = (rr >= 0) ? S[(size_t)rr * 256 + c4] : zero;
        }
        float4 p6 = f4add(f4add(f4add(nw[0], nw[1]), f4add(nw[2], nw[3])), f4add(nw[4], nw[5]));
        float4 s0 = f4add(f4add(prev0, prev1), p6);
        float4 s1 = f4add(prev1, f4add(p6, nw[6]));
        float4 s2 = f4add(p6, f4add(nw[6], nw[7]));
        float4 sv[3] = {s0, s1, s2};
        #pragma unroll
        for (int d = 0; d < 3; d++) {
            size_t row = (((size_t)(x * 3 + d)) * Bb + b) * Nn + t;
            __half2* dst = (__half2*)g_U + row * 512 + c4 * 2;
            dst[0] = __floats2half2_rn(sv[d].x, sv[d].y);
            dst[1] = __floats2half2_rn(sv[d].z, sv[d].w);
        }
        prev0 = nw[6];
        prev1 = nw[7];
    }
}

// ---------------------------------------------------------------------------
// Weight prep: transpose W [K,N] -> [N,K], round to fp16. Two weights per
// launch (zbase selects pair) so the projection GEMM is the 4th launch and
// lands in the ncu capture slot.
// ---------------------------------------------------------------------------
__global__ void __launch_bounds__(256) wprep_kernel(const float* __restrict__ Wa,
                                                    const float* __restrict__ Wb,
                                                    int zbase) {
    const int z = zbase + blockIdx.z;
    const float* W = (blockIdx.z == 0) ? Wa : Wb;
    __half* Oh = g_Wh + (size_t)z * 1024 * 1024;
    __shared__ float tile[32][33];
    const int n0 = blockIdx.x * 32, k0 = blockIdx.y * 32;
    const int tx = threadIdx.x & 31, ty = threadIdx.x >> 5;
    #pragma unroll
    for (int j = 0; j < 4; j++)
        tile[ty + j * 8][tx] = W[(size_t)(k0 + ty + j * 8) * 1024 + n0 + tx];
    __syncthreads();
    #pragma unroll
    for (int j = 0; j < 4; j++) {
        float val = tile[tx][ty + j * 8];
        Oh[(size_t)(n0 + ty + j * 8) * 1024 + k0 + tx] = __float2half_rn(val);
    }
}

// ---------------------------------------------------------------------------
// HMMA fp16 GEMM (round-6 structure, unchanged): C = A @ B^T, fp32 accum.
// CTA tile (64*MI) x 128, K-step 32, 3-stage cp.async, 8 warps (4M x 2N).
// SMEM rows padded to 80B. BCAST=1: broadcast rows into d_out.
// ---------------------------------------------------------------------------
#define BROWS 128

template <int MI, int BCAST>
__global__ void __launch_bounds__(256) gemm_tc(
        const __half* __restrict__ A,
        const __half* __restrict__ B0, const __half* __restrict__ B1,
        const __half* __restrict__ B2,
        void* __restrict__ Cv, const float* __restrict__ bias, int mblocks_per_x) {
    constexpr int CTAM = 64 * MI;
    constexpr int ASZ = CTAM * 80;
    constexpr int BSZ = BROWS * 80;
    constexpr int STAGE = ASZ + BSZ;

    extern __shared__ char dsm[];
    const uint32_t sbase = smem_u32(dsm);
    const int tid = threadIdx.x;
    const int wid = tid >> 5, lane = tid & 31;
    const int bn = blockIdx.x, bm = blockIdx.y;
    const int x = bm / mblocks_per_x;
    const __half* Bh = (x == 0) ? B0 : ((x == 1) ? B1 : B2);

    const int warpM = wid >> 1;          // 0..3
    const int warpN = wid & 1;           // 0..1
    const uint32_t aOff = (uint32_t)((warpM * 16 * MI + (lane & 15)) * 80 + (lane >> 4) * 16);
    const uint32_t bOff = (uint32_t)(ASZ +
        (warpN * 64 + ((lane >> 4) & 1) * 8 + (lane & 7)) * 80 + ((lane >> 3) & 1) * 16);

    float acc[MI][8][4];
    #pragma unroll
    for (int mi = 0; mi < MI; mi++)
        #pragma unroll
        for (int ni = 0; ni < 8; ni++)
            #pragma unroll
            for (int j = 0; j < 4; j++) acc[mi][ni][j] = 0.f;

    auto load_chunk = [&](int ch, int st) {
        const uint32_t bb = sbase + st * STAGE;
        const int kof = ch * 32;
        #pragma unroll
        for (int it = 0; it < MI; it++) {   // A: CTAM rows * 4 cp16 / 256 thr
            int idx = tid + it * 256;
            int r = idx >> 2, qq = idx & 3;
            uint32_t dst = bb + r * 80 + qq * 16;
            size_t g = (size_t)(bm * CTAM + r) * 1024 + kof + qq * 8;
            cp16(dst, A + g);
        }
        #pragma unroll
        for (int it = 0; it < 2; it++) {    // B: 128 rows * 4 cp16 / 256 thr
            int idx = tid + it * 256;
            int r = idx >> 2, qq = idx & 3;
            uint32_t dst = bb + ASZ + r * 80 + qq * 16;
            size_t g = (size_t)(bn * BROWS + r) * 1024 + kof + qq * 8;
            cp16(dst, Bh + g);
        }
        CP_COMMIT();
    };

    // Prologue: fill 2 of 3 stages
    load_chunk(0, 0);
    load_chunk(1, 1);

    for (int i = 0; i < 32; i++) {
        CP_WAIT1();              // chunk i resident (<=1 group still in flight)
        __syncthreads();         // all warps done with chunk i-1 before overwrite
        const uint32_t bb = sbase + (i % 3) * STAGE;
        #pragma unroll
        for (int kk = 0; kk < 2; kk++) {
            uint32_t ah[MI][4];
            #pragma unroll
            for (int mi = 0; mi < MI; mi++)
                ldsm_x4(ah[mi], bb + aOff + mi * 16 * 80 + kk * 32);
            #pragma unroll
            for (int p = 0; p < 4; p++) {   // 4 n-pairs = 8 n8 tiles
                uint32_t b4[4];
                ldsm_x4(b4, bb + bOff + p * 16 * 80 + kk * 32);
                #pragma unroll
                for (int mi = 0; mi < MI; mi++) {
                    mma_f16(acc[mi][2 * p],     ah[mi], b4);
                    mma_f16(acc[mi][2 * p + 1], ah[mi], b4 + 2);
                }
            }
        }
        if (i + 2 < 32) load_chunk(i + 2, (i + 2) % 3);
        else CP_COMMIT();        // keep group count uniform for wait_group
    }

    // Epilogue
    const int row0 = bm * CTAM + warpM * 16 * MI + (lane >> 2);
    const int col0 = bn * 128 + warpN * 64 + (lane & 3) * 2;
    #pragma unroll
    for (int mi = 0; mi < MI; mi++) {
        #pragma unroll
        for (int ni = 0; ni < 8; ni++) {
            int r = row0 + mi * 16;
            int c = col0 + ni * 8;
            if (BCAST) {
                float* C = (float*)Cv;
                float b0 = bias ? bias[c] : 0.f, b1 = bias ? bias[c + 1] : 0.f;
                float2 v0 = make_float2(acc[mi][ni][0] + b0, acc[mi][ni][1] + b1);
                float2 v1 = make_float2(acc[mi][ni][2] + b0, acc[mi][ni][3] + b1);
                int rb = r >> 8, rt = r & 255;
                float* o0 = C + ((size_t)rb * Ss + rt * 8) * 1024 + c;
                int r8 = r + 8;
                int rb2 = r8 >> 8, rt2 = r8 & 255;
                float* o1 = C + ((size_t)rb2 * Ss + rt2 * 8) * 1024 + c;
                #pragma unroll
                for (int rep = 0; rep < 8; rep++) {
                    *(float2*)(o0 + rep * 1024) = v0;
                    *(float2*)(o1 + rep * 1024) = v1;
                }
            } else {
                __half* C = (__half*)Cv;
                *(__half2*)&C[(size_t)r * 1024 + c] =
                    __floats2half2_rn(acc[mi][ni][0], acc[mi][ni][1]);
                *(__half2*)&C[(size_t)(r + 8) * 1024 + c] =
                    __floats2half2_rn(acc[mi][ni][2], acc[mi][ni][3]);
            }
        }
    }
}

// ---------------------------------------------------------------------------
// Combine: fold conv weights + biases + norm scale + /8 into pooled q/k/v.
// ---------------------------------------------------------------------------
__global__ void __launch_bounds__(256) combine_kernel(
        const float* __restrict__ wcq, const float* __restrict__ bcq, const float* __restrict__ bq,
        const float* __restrict__ wck, const float* __restrict__ bck, const float* __restrict__ bk,
        const float* __restrict__ wcv, const float* __restrict__ bcv, const float* __restrict__ bv) {
    const int t = blockIdx.x, b = blockIdx.y, x = blockIdx.z;
    const float* wc = (x == 0) ? wcq : ((x == 1) ? wck : wcv);
    const float* bc = (x == 0) ? bcq : ((x == 1) ? bck : bcv);
    const float* bd = (x == 0) ? bq  : ((x == 1) ? bk  : bv);
    const float scale = (x == 2) ? 1.0f : 0.35355339059327379f;  // 64^-0.25

    float cJ, c0, c1, c2;
    if (t == 0)      { cJ = 1.f; c0 = 0.f; c1 = 0.f; c2 = 1.f; }
    else if (t == 1) { cJ = 8.f; c0 = 7.f; c1 = 8.f; c2 = 8.f; }
    else             { cJ = 8.f; c0 = 8.f; c1 = 8.f; c2 = 8.f; }

    const size_t ds = (size_t)Bb * Nn * Dd;
    const size_t base0 = ((((size_t)x * 3 + 0) * Bb + b) * Nn + t) * Dd;

    for (int c = threadIdx.x; c < Dd; c += 256) {
        float G0 = __half2float(g_G[base0 + c]);
        float G1 = __half2float(g_G[base0 + ds + c]);
        float G2 = __half2float(g_G[base0 + 2 * ds + c]);
        float bdc = bd[c];
        float val = cJ * bc[c] + scale * (wc[c]          * (G0 + c0 * bdc) +
                                          wc[Dd + c]     * (G1 + c1 * bdc) +
                                          wc[2 * Dd + c] * (G2 + c2 * bdc));
        val *= 0.125f;
        int h = c >> 6, dd = c & 63;
        g_pool[((((size_t)x * Bb + b) * Hh + h) * Nn + t) * DDd + dd] = val;
    }
}

// ---------------------------------------------------------------------------
// Attention v2: grid (4 qtiles, 64 bh), 128 threads. Two threads per query,
// each owning 32 of the 64 dims; dot halves merged via shfl_xor over lane
// pairs. Key loop bound is warp-uniform (predicate applies causality), so
// the shuffle is always executed by converged lanes.
// ---------------------------------------------------------------------------
__global__ void __launch_bounds__(128) attn_kernel() {
    const int qt = blockIdx.x;          // 0..3 -> queries qt*64..qt*64+63
    const int bh = blockIdx.y;          // 0..63
    __shared__ float sK[64][DDd];
    __shared__ float sV[64][DDd];
    const float* qp = g_pool + ((size_t)0 * Bb * Hh + bh) * Nn * DDd;
    const float* kp = g_pool + ((size_t)1 * Bb * Hh + bh) * Nn * DDd;
    const float* vp = g_pool + ((size_t)2 * Bb * Hh + bh) * Nn * DDd;
    const int tid = threadIdx.x;
    const int wid = tid >> 5;
    const int qi = qt * 64 + (tid >> 1);        // query index
    const int hf = (tid & 1) * 32;              // dim half offset
    const int qiHiW = qt * 64 + wid * 16 + 15;  // highest query in this warp

    float qreg[32];
    #pragma unroll
    for (int d = 0; d < 32; d++) qreg[d] = qp[(size_t)qi * DDd + hf + d];

    float mi = -1e30f, li = 0.f;
    float acc[32];
    #pragma unroll
    for (int d = 0; d < 32; d++) acc[d] = 0.f;

    for (int t = 0; t <= qt; t++) {
        for (int idx = tid; idx < 64 * DDd / 4; idx += 128) {
            ((float4*)&sK[0][0])[idx] = ((const float4*)(kp + (size_t)t * 64 * DDd))[idx];
            ((float4*)&sV[0][0])[idx] = ((const float4*)(vp + (size_t)t * 64 * DDd))[idx];
        }
        __syncthreads();
        int mW = qiHiW - t * 64; if (mW > 63) mW = 63;      // warp-uniform
        int mMe = qi - t * 64;   if (mMe > 63) mMe = 63;     // per-query causal bound
        for (int m = 0; m <= mW; m++) {
            float d0 = 0.f, d1 = 0.f, d2 = 0.f, d3 = 0.f;
            #pragma unroll
            for (int d = 0; d < 32; d += 4) {
                d0 += qreg[d + 0] * sK[m][hf + d + 0];
                d1 += qreg[d + 1] * sK[m][hf + d + 1];
                d2 += qreg[d + 2] * sK[m][hf + d + 2];
                d3 += qreg[d + 3] * sK[m][hf + d + 3];
            }
            float half = (d0 + d1) + (d2 + d3);
            float dot = half + __shfl_xor_sync(0xffffffffu, half, 1);
            if (m <= mMe) {
                if (dot > mi) {
                    float f = __expf(mi - dot);
                    li *= f;
                    #pragma unroll
                    for (int d = 0; d < 32; d++) acc[d] *= f;
                    mi = dot;
                }
                float p = __expf(dot - mi);
                li += p;
                #pragma unroll
                for (int d = 0; d < 32; d++) acc[d] += p * sV[m][hf + d];
            }
        }
        __syncthreads();
    }

    float inv = 1.0f / li;
    float* outp = g_attn + ((size_t)bh * Nn + qi) * DDd + hf;
    #pragma unroll
    for (int d = 0; d < 32; d++) outp[d] = acc[d] * inv;
}

// ---------------------------------------------------------------------------
// Up-projection (Wup [64,64] per head) + merge -> fp16 rows for Wc GEMM
// ---------------------------------------------------------------------------
__global__ void __launch_bounds__(256) up_kernel(const float* __restrict__ Wup,
                                                 const float* __restrict__ bup) {
    const int bt = blockIdx.x;
    const int b = bt >> 8, t = bt & 255;
    __shared__ float sW[DDd * DDd];
    __shared__ float sIn[Hh * DDd];
    for (int idx = threadIdx.x; idx < DDd * DDd; idx += 256) sW[idx] = Wup[idx];
    for (int idx = threadIdx.x; idx < Hh * DDd; idx += 256) {
        int h = idx >> 6, dd = idx & 63;
        sIn[idx] = g_attn[(((size_t)b * Hh + h) * Nn + t) * DDd + dd];
    }
    __syncthreads();
    for (int c = threadIdx.x; c < Dd; c += 256) {
        int h = c >> 6, ddp = c & 63;
        float s = bup[ddp];
        #pragma unroll
        for (int dd = 0; dd < DDd; dd++) s += sIn[h * DDd + dd] * sW[dd * DDd + ddp];
        g_OP[((size_t)b * Nn + t) * Dd + c] = __float2half_rn(s);
    }
}

// ---------------------------------------------------------------------------
extern "C" void kernel_launch(void* const* d_in, const int* in_sizes, int n_in,
                              void* d_out, int out_size) {
    const float* q   = (const float*)d_in[0];
    const float* k   = (const float*)d_in[1];
    const float* v   = (const float*)d_in[2];
    const float* Wq  = (const float*)d_in[3];
    const float* bq  = (const float*)d_in[4];
    const float* Wk  = (const float*)d_in[5];
    const float* bk  = (const float*)d_in[6];
    const float* Wv  = (const float*)d_in[7];
    const float* bv  = (const float*)d_in[8];
    const float* Wup = (const float*)d_in[9];
    const float* bup = (const float*)d_in[10];
    const float* Wc  = (const float*)d_in[11];
    const float* bc  = (const float*)d_in[12];
    const float* wcq = (const float*)d_in[13];
    const float* bcq = (const float*)d_in[14];
    const float* wck = (const float*)d_in[15];
    const float* bck = (const float*)d_in[16];
    const float* wcv = (const float*)d_in[17];
    const float* bcv = (const float*)d_in[18];

    __half *pU, *pWh, *pOP, *pG;
    cudaGetSymbolAddress((void**)&pU, g_U);
    cudaGetSymbolAddress((void**)&pWh, g_Wh);
    cudaGetSymbolAddress((void**)&pOP, g_OP);
    cudaGetSymbolAddress((void**)&pG, g_G);

    const int SM2 = 3 * (128 * 80 + 128 * 80);
    const int SM1 = 3 * (64 * 80 + 128 * 80);
    cudaFuncSetAttribute((const void*)gemm_tc<2, 0>, cudaFuncAttributeMaxDynamicSharedMemorySize, SM2);
    cudaFuncSetAttribute((const void*)gemm_tc<1, 1>, cudaFuncAttributeMaxDynamicSharedMemorySize, SM1);

    // 1+2. Weight transpose + fp16 round, split so GEMM is launch #4
    wprep_kernel<<<dim3(32, 32, 2), 256>>>(Wq, Wk, 0);
    wprep_kernel<<<dim3(32, 32, 2), 256>>>(Wv, Wc, 2);

    // 3. Pooled GEMM inputs (dw-conv decomposition + causal pool), fp16
    pool_kernel<<<dim3(Nn / TSTEP, Bb, 3), 256>>>(q, k, v);

    // 4. Fused projection GEMMs (ncu capture slot): [9216,1024] @ [1024,1024]^T
    const size_t wstep = (size_t)1024 * 1024;
    gemm_tc<2, 0><<<dim3(8, 72), 256, SM2>>>(
        pU, pWh + 0 * wstep, pWh + 1 * wstep, pWh + 2 * wstep,
        pG, nullptr, 24);

    // 5. Combine conv weights/biases/scale -> pooled q/k/v
    combine_kernel<<<dim3(Nn, Bb, 3), 256>>>(wcq, bcq, bq, wck, bck, bk, wcv, bcv, bv);

    // 6. Causal attention over pooled tokens (256 CTAs)
    attn_kernel<<<dim3(4, Bb * Hh), 128>>>();

    // 7. Per-head Wup + merge heads -> fp16
    up_kernel<<<Bb * Nn, 256>>>(Wup, bup);

    // 8. Final dense Wc (+bias), epilogue broadcasts each row to 8 seq positions
    gemm_tc<1, 1><<<dim3(8, 16), 256, SM1>>>(
        pOP, pWh + 3 * wstep, pWh + 3 * wstep, pWh + 3 * wstep,
        (void*)d_out, bc, 16);
}